// round 1
// baseline (speedup 1.0000x reference)
#include <cuda_runtime.h>
#include <cuda_bf16.h>
#include <cstdint>

// ---------------------------------------------------------------------------
// DeformableAttention (MSDA): B=8, C=256, H=8 heads, d=32, Lv=4 levels, P=4 pts
// Pipeline:
//   GEMM1: value = input_flatten @ W_val + b_val          -> g_value [B*L, 256]
//   GEMM2a: off  = query @ W_off + b_off                  -> g_off   [B*Nq,256]
//   GEMM2b: aw   = query @ W_attn + b_attn                -> g_attn  [B*Nq,128]
//   SAMPLE: softmax + bilinear gather + weighted sum      -> g_msda  [B*Nq,256]
//   GEMM3: out  = g_msda @ W_out + b_out                  -> d_out
// All fp32. GEMMs use fma.rn.f32x2 (packed Blackwell FFMA2, 2x fp32 FMA rate).
// ---------------------------------------------------------------------------

#define MAXROWS 106496ull  // >= B*Nq = 8*13294 = 106352, padded

__device__ float g_value[MAXROWS * 256];
__device__ float g_off  [MAXROWS * 256];
__device__ float g_attn [MAXROWS * 128];
__device__ float g_msda [MAXROWS * 256];

// ---- packed f32x2 helpers --------------------------------------------------
__device__ __forceinline__ unsigned long long pack2(float lo, float hi) {
    unsigned long long r;
    asm("mov.b64 %0, {%1, %2};" : "=l"(r)
        : "r"(__float_as_uint(lo)), "r"(__float_as_uint(hi)));
    return r;
}
__device__ __forceinline__ void unpack2(unsigned long long v, float& lo, float& hi) {
    unsigned int a, b;
    asm("mov.b64 {%0, %1}, %2;" : "=r"(a), "=r"(b) : "l"(v));
    lo = __uint_as_float(a);
    hi = __uint_as_float(b);
}
#define FFMA2(d, a, b) \
    asm("fma.rn.f32x2 %0, %1, %2, %0;" : "+l"(d) : "l"(a), "l"(b))

// ---- SGEMM: A[M,256] @ W[256,N] + bias[N] -> Cmat[M,N]  (N multiple of 128)
// 128x128 tile, BK=16, 256 threads, 8x8 per-thread microtile via f32x2.
__global__ __launch_bounds__(256) void sgemm256(
    const float* __restrict__ A, const float* __restrict__ W,
    const float* __restrict__ bias, float* __restrict__ Cmat,
    int M, int N)
{
    constexpr int BM = 128, BN = 128, BK = 16;
    __shared__ float As[BK][BM];
    __shared__ float Bs[BK][BN];

    const int tid = threadIdx.x;
    const int bm = blockIdx.y * BM;
    const int bn = blockIdx.x * BN;
    const int tx = tid & 15;   // 16 col-threads
    const int ty = tid >> 4;   // 16 row-threads

    unsigned long long acc[8][4];
#pragma unroll
    for (int i = 0; i < 8; i++)
#pragma unroll
        for (int j = 0; j < 4; j++) acc[i][j] = 0ull;

    const int arow = tid >> 2;        // 0..63 (+64 second pass)
    const int acol = (tid & 3) * 4;   // 0,4,8,12
    const int brow = tid >> 5;        // 0..7  (+8 second pass)
    const int bcol = (tid & 31) * 4;  // 0..124

    for (int k0 = 0; k0 < 256; k0 += BK) {
#pragma unroll
        for (int i = 0; i < 2; i++) {
            int r = arow + i * 64;
            float4 v = make_float4(0.f, 0.f, 0.f, 0.f);
            if (bm + r < M)
                v = *(const float4*)(A + (size_t)(bm + r) * 256 + k0 + acol);
            As[acol + 0][r] = v.x; As[acol + 1][r] = v.y;
            As[acol + 2][r] = v.z; As[acol + 3][r] = v.w;
        }
#pragma unroll
        for (int i = 0; i < 2; i++) {
            int r = brow + i * 8;
            *(float4*)&Bs[r][bcol] =
                *(const float4*)(W + (size_t)(k0 + r) * N + bn + bcol);
        }
        __syncthreads();
#pragma unroll
        for (int k = 0; k < BK; k++) {
            unsigned long long b2[4];
            const unsigned long long* bs64 =
                (const unsigned long long*)&Bs[k][tx * 8];
#pragma unroll
            for (int j = 0; j < 4; j++) b2[j] = bs64[j];
#pragma unroll
            for (int i = 0; i < 8; i++) {
                float av = As[k][ty * 8 + i];
                unsigned long long a2 = pack2(av, av);
#pragma unroll
                for (int j = 0; j < 4; j++) FFMA2(acc[i][j], a2, b2[j]);
            }
        }
        __syncthreads();
    }

#pragma unroll
    for (int i = 0; i < 8; i++) {
        int row = bm + ty * 8 + i;
        if (row < M) {
#pragma unroll
            for (int j = 0; j < 4; j++) {
                float lo, hi;
                unpack2(acc[i][j], lo, hi);
                int col = bn + tx * 8 + j * 2;
                Cmat[(size_t)row * N + col + 0] = lo + bias[col + 0];
                Cmat[(size_t)row * N + col + 1] = hi + bias[col + 1];
            }
        }
    }
}

// ---- sampling kernel: one warp per (b,q,h); lane = channel d ---------------
__global__ __launch_bounds__(256) void msda_sample(
    const float* __restrict__ rp,     // [B,Nq,4,2]
    const int*   __restrict__ shapes, // [4,2]
    int M)                             // B*Nq rows
{
    __shared__ int sh[4], sw[4], sstart[4], sL[1];
    if (threadIdx.x == 0) {
        int st = 0;
        for (int l = 0; l < 4; l++) {
            sh[l] = shapes[2 * l];
            sw[l] = shapes[2 * l + 1];
            sstart[l] = st;
            st += sh[l] * sw[l];
        }
        sL[0] = st;
    }
    __syncthreads();
    const int Ltot = sL[0];

    const int lane = threadIdx.x & 31;
    const int warp = threadIdx.x >> 5;
    const long long gw = (long long)blockIdx.x * 8 + warp;
    const int h = (int)(gw & 7);
    const long long t = gw >> 3;        // = b*Nq + q  (Nq == L)
    if (t >= M) return;
    const int b = (int)(t / Ltot);

    // softmax over 16 attn logits (lanes 0..15 hold points l*4+p)
    float logit = -1e30f;
    if (lane < 16) logit = g_attn[t * 128 + h * 16 + lane];
    float mx = logit;
#pragma unroll
    for (int s = 8; s; s >>= 1) mx = fmaxf(mx, __shfl_xor_sync(0xffffffffu, mx, s));
    float e = (lane < 16) ? expf(logit - mx) : 0.f;
    float ssum = e;
#pragma unroll
    for (int s = 8; s; s >>= 1) ssum += __shfl_xor_sync(0xffffffffu, ssum, s);
    const float wsm = e / ssum;

    // per-head offsets: lane = l*8 + p*2 + c
    const float offv = g_off[t * 256 + h * 32 + lane];
    const float refv = (lane < 8) ? rp[t * 8 + lane] : 0.f;

    float acc = 0.f;
    const float* vbase = g_value + (long long)b * Ltot * 256 + h * 32 + lane;

#pragma unroll
    for (int l = 0; l < 4; l++) {
        const float rx = __shfl_sync(0xffffffffu, refv, 2 * l);
        const float ry = __shfl_sync(0xffffffffu, refv, 2 * l + 1);
        const int w_ = sw[l], h_ = sh[l], start = sstart[l];
        const float fw = (float)w_, fh = (float)h_;
#pragma unroll
        for (int p = 0; p < 4; p++) {
            const float ox = __shfl_sync(0xffffffffu, offv, l * 8 + p * 2);
            const float oy = __shfl_sync(0xffffffffu, offv, l * 8 + p * 2 + 1);
            const float aw = __shfl_sync(0xffffffffu, wsm, l * 4 + p);
            const float x = (rx + ox) * fw - 0.5f;
            const float y = (ry + oy) * fh - 0.5f;
            const float x0f = floorf(x), y0f = floorf(y);
            const float fx = x - x0f, fy = y - y0f;
            const int x0 = (int)x0f, y0 = (int)y0f;
            const bool xin0 = (x0 >= 0) && (x0 < w_);
            const bool xin1 = (x0 + 1 >= 0) && (x0 + 1 < w_);
            const bool yin0 = (y0 >= 0) && (y0 < h_);
            const bool yin1 = (y0 + 1 >= 0) && (y0 + 1 < h_);
            float v00 = 0.f, v10 = 0.f, v01 = 0.f, v11 = 0.f;
            const long long base0 = ((long long)start + (long long)y0 * w_) * 256;
            if (yin0) {
                if (xin0) v00 = vbase[base0 + (long long)x0 * 256];
                if (xin1) v10 = vbase[base0 + (long long)(x0 + 1) * 256];
            }
            if (yin1) {
                const long long base1 = base0 + (long long)w_ * 256;
                if (xin0) v01 = vbase[base1 + (long long)x0 * 256];
                if (xin1) v11 = vbase[base1 + (long long)(x0 + 1) * 256];
            }
            const float bil = (v00 * (1.f - fx) + v10 * fx) * (1.f - fy)
                            + (v01 * (1.f - fx) + v11 * fx) * fy;
            acc = fmaf(aw, bil, acc);
        }
    }
    g_msda[t * 256 + h * 32 + lane] = acc;
}

// ---------------------------------------------------------------------------
extern "C" void kernel_launch(void* const* d_in, const int* in_sizes, int n_in,
                              void* d_out, int out_size)
{
    const float* query   = (const float*)d_in[0];
    const float* rp      = (const float*)d_in[1];
    const float* flat    = (const float*)d_in[2];
    const int*   shapes  = (const int*)  d_in[3];
    const float* W_off   = (const float*)d_in[4];
    const float* b_off   = (const float*)d_in[5];
    const float* W_attn  = (const float*)d_in[6];
    const float* b_attn  = (const float*)d_in[7];
    const float* W_val   = (const float*)d_in[8];
    const float* b_val   = (const float*)d_in[9];
    const float* W_out   = (const float*)d_in[10];
    const float* b_out   = (const float*)d_in[11];
    float* out = (float*)d_out;

    const int M = in_sizes[0] / 256;   // B*Nq rows (== B*L)

    float *pv, *po, *pa, *pm;
    cudaGetSymbolAddress((void**)&pv, g_value);
    cudaGetSymbolAddress((void**)&po, g_off);
    cudaGetSymbolAddress((void**)&pa, g_attn);
    cudaGetSymbolAddress((void**)&pm, g_msda);

    const int mtiles = (M + 127) / 128;
    dim3 blk(256);

    // GEMM1: value projection
    sgemm256<<<dim3(2, mtiles), blk>>>(flat, W_val, b_val, pv, M, 256);
    // GEMM2a: sampling offsets
    sgemm256<<<dim3(2, mtiles), blk>>>(query, W_off, b_off, po, M, 256);
    // GEMM2b: attention logits
    sgemm256<<<dim3(1, mtiles), blk>>>(query, W_attn, b_attn, pa, M, 128);
    // sampling: one warp per (b,q,h): M*8 warps, 8 warps/block -> M blocks
    msda_sample<<<dim3(M), blk>>>(rp, shapes, M);
    // GEMM3: output projection
    sgemm256<<<dim3(2, mtiles), blk>>>(pm, W_out, b_out, out, M, 256);
}

// round 2
// speedup vs baseline: 1.4881x; 1.4881x over previous
#include <cuda_runtime.h>
#include <cuda_bf16.h>
#include <cstdint>

// ---------------------------------------------------------------------------
// DeformableAttention (MSDA): B=8, C=256, H=8 heads, d=32, Lv=4 levels, P=4 pts
//   GEMM1 : value = input_flatten @ W_val + b_val      -> g_value [B*L, 256]
//   GEMM2a: off   = query @ W_off  + b_off             -> g_off   [B*Nq,256]
//   GEMM2b: aw    = query @ W_attn + b_attn            -> g_attn  [B*Nq,128]
//   SAMPLE: softmax + bilinear gather + weighted sum   -> g_msda  [B*Nq,256]
//   GEMM3 : out   = g_msda @ W_out + b_out             -> d_out
// GEMMs: fma.rn.f32x2 SIMT. Sampler v2: 4 heads/warp, float4 lanes,
// owner/consumer point split, int32 addressing.
// ---------------------------------------------------------------------------

#define MAXROWS 106496ull  // >= B*Nq = 8*13294, padded

__device__ float g_value[MAXROWS * 256];
__device__ float g_off  [MAXROWS * 256];
__device__ float g_attn [MAXROWS * 128];
__device__ float g_msda [MAXROWS * 256];

// ---- packed f32x2 helpers --------------------------------------------------
__device__ __forceinline__ unsigned long long pack2(float lo, float hi) {
    unsigned long long r;
    asm("mov.b64 %0, {%1, %2};" : "=l"(r)
        : "r"(__float_as_uint(lo)), "r"(__float_as_uint(hi)));
    return r;
}
__device__ __forceinline__ void unpack2(unsigned long long v, float& lo, float& hi) {
    unsigned int a, b;
    asm("mov.b64 {%0, %1}, %2;" : "=r"(a), "=r"(b) : "l"(v));
    lo = __uint_as_float(a);
    hi = __uint_as_float(b);
}
#define FFMA2(d, a, b) \
    asm("fma.rn.f32x2 %0, %1, %2, %0;" : "+l"(d) : "l"(a), "l"(b))

// ---- SGEMM: A[M,256] @ W[256,N] + bias[N] -> Cmat[M,N]  (N multiple of 128)
__global__ __launch_bounds__(256) void sgemm256(
    const float* __restrict__ A, const float* __restrict__ W,
    const float* __restrict__ bias, float* __restrict__ Cmat,
    int M, int N)
{
    constexpr int BM = 128, BN = 128, BK = 16;
    __shared__ float As[BK][BM];
    __shared__ float Bs[BK][BN];

    const int tid = threadIdx.x;
    const int bm = blockIdx.y * BM;
    const int bn = blockIdx.x * BN;
    const int tx = tid & 15;
    const int ty = tid >> 4;

    unsigned long long acc[8][4];
#pragma unroll
    for (int i = 0; i < 8; i++)
#pragma unroll
        for (int j = 0; j < 4; j++) acc[i][j] = 0ull;

    const int arow = tid >> 2;
    const int acol = (tid & 3) * 4;
    const int brow = tid >> 5;
    const int bcol = (tid & 31) * 4;

    for (int k0 = 0; k0 < 256; k0 += BK) {
#pragma unroll
        for (int i = 0; i < 2; i++) {
            int r = arow + i * 64;
            float4 v = make_float4(0.f, 0.f, 0.f, 0.f);
            if (bm + r < M)
                v = *(const float4*)(A + (size_t)(bm + r) * 256 + k0 + acol);
            As[acol + 0][r] = v.x; As[acol + 1][r] = v.y;
            As[acol + 2][r] = v.z; As[acol + 3][r] = v.w;
        }
#pragma unroll
        for (int i = 0; i < 2; i++) {
            int r = brow + i * 8;
            *(float4*)&Bs[r][bcol] =
                *(const float4*)(W + (size_t)(k0 + r) * N + bn + bcol);
        }
        __syncthreads();
#pragma unroll
        for (int k = 0; k < BK; k++) {
            unsigned long long b2[4];
            const unsigned long long* bs64 =
                (const unsigned long long*)&Bs[k][tx * 8];
#pragma unroll
            for (int j = 0; j < 4; j++) b2[j] = bs64[j];
#pragma unroll
            for (int i = 0; i < 8; i++) {
                float av = As[k][ty * 8 + i];
                unsigned long long a2 = pack2(av, av);
#pragma unroll
                for (int j = 0; j < 4; j++) FFMA2(acc[i][j], a2, b2[j]);
            }
        }
        __syncthreads();
    }

#pragma unroll
    for (int i = 0; i < 8; i++) {
        int row = bm + ty * 8 + i;
        if (row < M) {
#pragma unroll
            for (int j = 0; j < 4; j++) {
                float lo, hi;
                unpack2(acc[i][j], lo, hi);
                int col = bn + tx * 8 + j * 2;
                Cmat[(size_t)row * N + col + 0] = lo + bias[col + 0];
                Cmat[(size_t)row * N + col + 1] = hi + bias[col + 1];
            }
        }
    }
}

// ---- sampler v2: 4 heads per warp, 8 lanes/head (lane = 4 channels float4) -
// Each lane OWNS 2 of the 16 sampling points for its head: computes softmax
// weight, combined bilinear*valid*aw weights, and packed int32 index/steps.
// Consumers shuffle 6 words/point and do 4 LDG.128 + 16 FMA.
__global__ __launch_bounds__(256) void msda_sample_v2(
    const float* __restrict__ rp,     // [B,Nq,4,2]
    const int*   __restrict__ shapes, // [4,2]
    int M)                             // B*Nq rows
{
    __shared__ int s_w[4], s_h[4], s_start[4];
    __shared__ float s_fw[4], s_fh[4];
    __shared__ int s_L;
    if (threadIdx.x == 0) {
        int st = 0;
        for (int l = 0; l < 4; l++) {
            int hh = shapes[2 * l], ww = shapes[2 * l + 1];
            s_h[l] = hh; s_w[l] = ww; s_start[l] = st;
            s_fh[l] = (float)hh; s_fw[l] = (float)ww;
            st += hh * ww;
        }
        s_L = st;
    }
    __syncthreads();
    const int Ltot = s_L;

    const unsigned FULL = 0xffffffffu;
    const int lane = threadIdx.x & 31;
    const int warp = threadIdx.x >> 5;
    const int t = blockIdx.x * 4 + (warp >> 1);   // query row
    if (t >= M) return;
    const int h   = (warp & 1) * 4 + (lane >> 3); // head 0..7
    const int sub = lane & 7;                      // channel group (4 ch each)
    const int b   = t / Ltot;

    // ---------- owner phase: points pt = sub*2, sub*2+1 ----------
    float logit0, logit1;
    int   pi[2], pst[2];
    float pc00[2], pc10[2], pc01[2], pc11[2];

    {
        const float* ab = g_attn + (size_t)t * 128 + h * 16;
        logit0 = ab[sub * 2];
        logit1 = ab[sub * 2 + 1];
    }
    // softmax over the 16 logits of this head (8-lane group reduce)
    float mx = fmaxf(logit0, logit1);
#pragma unroll
    for (int s = 4; s; s >>= 1) mx = fmaxf(mx, __shfl_xor_sync(FULL, mx, s));
    float e0 = expf(logit0 - mx), e1 = expf(logit1 - mx);
    float sm = e0 + e1;
#pragma unroll
    for (int s = 4; s; s >>= 1) sm += __shfl_xor_sync(FULL, sm, s);
    const float inv = 1.f / sm;

#pragma unroll
    for (int s = 0; s < 2; s++) {
        const int pt = sub * 2 + s;
        const int l  = pt >> 2;
        const float aw = (s ? e1 : e0) * inv;
        float2 off = *(const float2*)(g_off + (size_t)t * 256 + h * 32 + pt * 2);
        float2 ref = *(const float2*)(rp + (size_t)t * 8 + l * 2);
        const int w_ = s_w[l], h_ = s_h[l];
        const float x = (ref.x + off.x) * s_fw[l] - 0.5f;
        const float y = (ref.y + off.y) * s_fh[l] - 0.5f;
        const float x0f = floorf(x), y0f = floorf(y);
        const float fx = x - x0f, fy = y - y0f;
        const int x0 = (int)x0f, y0 = (int)y0f;
        const float m00 = ((x0 >= 0)     & (x0 < w_)     & (y0 >= 0)     & (y0 < h_))     ? 1.f : 0.f;
        const float m10 = ((x0 + 1 >= 0) & (x0 + 1 < w_) & (y0 >= 0)     & (y0 < h_))     ? 1.f : 0.f;
        const float m01 = ((x0 >= 0)     & (x0 < w_)     & (y0 + 1 >= 0) & (y0 + 1 < h_)) ? 1.f : 0.f;
        const float m11 = ((x0 + 1 >= 0) & (x0 + 1 < w_) & (y0 + 1 >= 0) & (y0 + 1 < h_)) ? 1.f : 0.f;
        const int xc0 = min(max(x0, 0), w_ - 1);
        const int xc1 = min(max(x0 + 1, 0), w_ - 1);
        const int yc0 = min(max(y0, 0), h_ - 1);
        const int yc1 = min(max(y0 + 1, 0), h_ - 1);
        pi[s]  = s_start[l] + yc0 * w_ + xc0;
        pst[s] = (xc1 - xc0) | ((yc1 - yc0) * w_ << 16);
        const float gx1 = fx, gx0 = 1.f - fx;
        const float gy1 = fy, gy0 = 1.f - fy;
        pc00[s] = gx0 * gy0 * m00 * aw;
        pc10[s] = gx1 * gy0 * m10 * aw;
        pc01[s] = gx0 * gy1 * m01 * aw;
        pc11[s] = gx1 * gy1 * m11 * aw;
    }

    // ---------- consumer phase: all 16 points, float4 per lane ----------
    const float4* vp = (const float4*)g_value + (size_t)b * Ltot * 64 + h * 8 + sub;
    float4 acc = make_float4(0.f, 0.f, 0.f, 0.f);

#pragma unroll
    for (int pt = 0; pt < 16; pt++) {
        const int src  = pt >> 1;
        const int slot = pt & 1;
        const int   i00 = slot ? __shfl_sync(FULL, pi[1],   src, 8) : __shfl_sync(FULL, pi[0],   src, 8);
        const int   st  = slot ? __shfl_sync(FULL, pst[1],  src, 8) : __shfl_sync(FULL, pst[0],  src, 8);
        const float c00 = slot ? __shfl_sync(FULL, pc00[1], src, 8) : __shfl_sync(FULL, pc00[0], src, 8);
        const float c10 = slot ? __shfl_sync(FULL, pc10[1], src, 8) : __shfl_sync(FULL, pc10[0], src, 8);
        const float c01 = slot ? __shfl_sync(FULL, pc01[1], src, 8) : __shfl_sync(FULL, pc01[0], src, 8);
        const float c11 = slot ? __shfl_sync(FULL, pc11[1], src, 8) : __shfl_sync(FULL, pc11[0], src, 8);
        const int cs = st & 0xffff;
        const int rs = st >> 16;
        const float4* q = vp + (size_t)i00 * 64;
        const float4 v00 = q[0];
        const float4 v10 = q[cs * 64];
        const float4 v01 = q[rs * 64];
        const float4 v11 = q[(cs + rs) * 64];
        acc.x = fmaf(c00, v00.x, fmaf(c10, v10.x, fmaf(c01, v01.x, fmaf(c11, v11.x, acc.x))));
        acc.y = fmaf(c00, v00.y, fmaf(c10, v10.y, fmaf(c01, v01.y, fmaf(c11, v11.y, acc.y))));
        acc.z = fmaf(c00, v00.z, fmaf(c10, v10.z, fmaf(c01, v01.z, fmaf(c11, v11.z, acc.z))));
        acc.w = fmaf(c00, v00.w, fmaf(c10, v10.w, fmaf(c01, v01.w, fmaf(c11, v11.w, acc.w))));
    }

    *(float4*)(g_msda + (size_t)t * 256 + h * 32 + sub * 4) = acc;
}

// ---------------------------------------------------------------------------
extern "C" void kernel_launch(void* const* d_in, const int* in_sizes, int n_in,
                              void* d_out, int out_size)
{
    const float* query   = (const float*)d_in[0];
    const float* rp      = (const float*)d_in[1];
    const float* flat    = (const float*)d_in[2];
    const int*   shapes  = (const int*)  d_in[3];
    const float* W_off   = (const float*)d_in[4];
    const float* b_off   = (const float*)d_in[5];
    const float* W_attn  = (const float*)d_in[6];
    const float* b_attn  = (const float*)d_in[7];
    const float* W_val   = (const float*)d_in[8];
    const float* b_val   = (const float*)d_in[9];
    const float* W_out   = (const float*)d_in[10];
    const float* b_out   = (const float*)d_in[11];
    float* out = (float*)d_out;

    const int M = in_sizes[0] / 256;   // B*Nq rows

    float *pv, *po, *pa, *pm;
    cudaGetSymbolAddress((void**)&pv, g_value);
    cudaGetSymbolAddress((void**)&po, g_off);
    cudaGetSymbolAddress((void**)&pa, g_attn);
    cudaGetSymbolAddress((void**)&pm, g_msda);

    const int mtiles = (M + 127) / 128;
    dim3 blk(256);

    sgemm256<<<dim3(2, mtiles), blk>>>(flat, W_val, b_val, pv, M, 256);
    sgemm256<<<dim3(2, mtiles), blk>>>(query, W_off, b_off, po, M, 256);
    sgemm256<<<dim3(1, mtiles), blk>>>(query, W_attn, b_attn, pa, M, 128);
    msda_sample_v2<<<dim3((M + 3) / 4), blk>>>(rp, shapes, M);
    sgemm256<<<dim3(2, mtiles), blk>>>(pm, W_out, b_out, out, M, 256);
}

// round 4
// speedup vs baseline: 2.6402x; 1.7742x over previous
#include <cuda_runtime.h>
#include <cuda_bf16.h>
#include <cstdint>

// ---------------------------------------------------------------------------
// DeformableAttention (MSDA): B=8, C=256, H=8, d=32, Lv=4, P=4
//   wt_convert : pre-transpose + bf16-split weights -> g_wt_hi/lo [896,256]
//   gemm_mma   : mma.sync bf16 3-term-split GEMM (fp32 in/out, fp32 accum)
//   msda_sample: softmax + bilinear gather (v2)
// GEMM: 128x128 CTA tile, 8 warps x (32x64), m16n8k16, ldmatrix fragments,
//       K=256 in 4 chunks of 64, reg-prefetch pipeline.
// off+attn GEMMs fused into one N=384 GEMM -> g_offattn.
// ---------------------------------------------------------------------------

#define MAXROWS 106496ull  // >= B*Nq = 8*13294, padded to 128

__device__ float g_value  [MAXROWS * 256];
__device__ float g_offattn[MAXROWS * 384];  // [:,0:256)=off, [:,256:384)=attn
__device__ float g_msda   [MAXROWS * 256];

// transposed split weights: rows 0-255 = W_val^T, 256-511 = W_off^T,
// 512-639 = W_attn^T, 640-895 = W_out^T ; each row = 256 K-values
__device__ __align__(16) __nv_bfloat16 g_wt_hi[896 * 256];
__device__ __align__(16) __nv_bfloat16 g_wt_lo[896 * 256];

// ---- helpers ----------------------------------------------------------------
__device__ __forceinline__ uint32_t smem_u32(const void* p) {
    uint32_t a;
    asm("{ .reg .u64 t; cvta.to.shared.u64 t, %1; cvt.u32.u64 %0, t; }"
        : "=r"(a) : "l"(p));
    return a;
}
__device__ __forceinline__ void ldm_x4(uint32_t* r, uint32_t addr) {
    asm volatile("ldmatrix.sync.aligned.m8n8.x4.shared.b16 {%0,%1,%2,%3}, [%4];"
                 : "=r"(r[0]), "=r"(r[1]), "=r"(r[2]), "=r"(r[3]) : "r"(addr));
}
__device__ __forceinline__ void mma16816(float* d, const uint32_t* a,
                                         uint32_t b0, uint32_t b1) {
    asm volatile(
        "mma.sync.aligned.m16n8k16.row.col.f32.bf16.bf16.f32 "
        "{%0,%1,%2,%3}, {%4,%5,%6,%7}, {%8,%9}, {%0,%1,%2,%3};"
        : "+f"(d[0]), "+f"(d[1]), "+f"(d[2]), "+f"(d[3])
        : "r"(a[0]), "r"(a[1]), "r"(a[2]), "r"(a[3]), "r"(b0), "r"(b1));
}
__device__ __forceinline__ uint32_t pack_bf16x2(float x, float y) {
    __nv_bfloat162 t(__float2bfloat16(x), __float2bfloat16(y));
    return *(uint32_t*)&t;
}

// ---- weight pre-transpose + split kernel ------------------------------------
__global__ void wt_convert(const float* __restrict__ Wv, const float* __restrict__ Wo,
                           const float* __restrict__ Wa, const float* __restrict__ Wu) {
    int idx = blockIdx.x * 256 + threadIdx.x;   // 896*256 total
    if (idx >= 896 * 256) return;
    int n = idx >> 8, k = idx & 255;
    float v;
    if      (n < 256) v = Wv[k * 256 + n];
    else if (n < 512) v = Wo[k * 256 + (n - 256)];
    else if (n < 640) v = Wa[k * 128 + (n - 512)];
    else              v = Wu[k * 256 + (n - 640)];
    __nv_bfloat16 hi = __float2bfloat16(v);
    __nv_bfloat16 lo = __float2bfloat16(v - __bfloat162float(hi));
    g_wt_hi[n * 256 + k] = hi;
    g_wt_lo[n * 256 + k] = lo;
}

// ---- mma.sync GEMM -----------------------------------------------------------
// C[M,N] = A[M,256] @ W^T(rows wtrow..wtrow+N) ; bias routed at col nsplit.
// SMEM: 4 tiles of 128 rows x 64 bf16, padded row stride 72 elems (144 B).
#define RS 72
#define TILE_B (128 * RS * 2)         // 18432 bytes
#define SM_GEMM (4 * TILE_B)          // 73728 bytes

__global__ __launch_bounds__(256) void gemm_mma(
    const float* __restrict__ A, int wtrow,
    const float* __restrict__ bias1, const float* __restrict__ bias2, int nsplit,
    float* __restrict__ C, int ldc, int M, int N)
{
    extern __shared__ char smem[];
    const uint32_t sAh = smem_u32(smem);
    const uint32_t sAl = sAh + TILE_B;
    const uint32_t sBh = sAh + 2 * TILE_B;
    const uint32_t sBl = sAh + 3 * TILE_B;

    const int tid  = threadIdx.x;
    const int lane = tid & 31;
    const int wid  = tid >> 5;
    const int wm   = wid & 3;        // m-group: rows wm*32..+31
    const int wn   = wid >> 2;       // n-group: cols wn*64..+63
    const int bm   = blockIdx.y * 128;
    const int bn   = blockIdx.x * 128;

    // loader mapping: 16 k-lanes x 16 rows, 8 row-iters
    const int g  = tid & 15;
    const int r0 = tid >> 4;

    float4 pa[8];
    uint2  pbh[8], pbl[8];

    // prefetch chunk 0
#pragma unroll
    for (int i = 0; i < 8; i++) {
        const int row = bm + r0 + i * 16;
        pa[i] = make_float4(0.f, 0.f, 0.f, 0.f);
        if (row < M) pa[i] = *(const float4*)(A + (size_t)row * 256 + g * 4);
        const size_t src = (size_t)(wtrow + bn + r0 + i * 16) * 256 + g * 4;
        pbh[i] = *(const uint2*)(g_wt_hi + src);
        pbl[i] = *(const uint2*)(g_wt_lo + src);
    }

    float acc[2][8][4];
#pragma unroll
    for (int mi = 0; mi < 2; mi++)
#pragma unroll
        for (int j = 0; j < 8; j++)
#pragma unroll
            for (int q = 0; q < 4; q++) acc[mi][j][q] = 0.f;

    // per-lane ldmatrix offsets
    const int fr  = lane & 15;               // fragment row
    const int fc  = (lane >> 4) << 3;        // fragment col (0 or 8)
    const uint32_t aoff = (uint32_t)(((wm * 32 + fr) * RS + fc) * 2);
    const uint32_t boff = (uint32_t)(((wn * 64 + fr) * RS + fc) * 2);

    for (int c = 0; c < 4; c++) {
        // ---- stage chunk c into SMEM ----
#pragma unroll
        for (int i = 0; i < 8; i++) {
            const uint32_t off = (uint32_t)(((r0 + i * 16) * RS + g * 4) * 2);
            uint2 uh, ul;
            uh.x = pack_bf16x2(pa[i].x, pa[i].y);
            uh.y = pack_bf16x2(pa[i].z, pa[i].w);
            __nv_bfloat162 h0 = *(__nv_bfloat162*)&uh.x;
            __nv_bfloat162 h1 = *(__nv_bfloat162*)&uh.y;
            ul.x = pack_bf16x2(pa[i].x - __bfloat162float(h0.x),
                               pa[i].y - __bfloat162float(h0.y));
            ul.y = pack_bf16x2(pa[i].z - __bfloat162float(h1.x),
                               pa[i].w - __bfloat162float(h1.y));
            *(uint2*)(smem + (off))              = uh;
            *(uint2*)(smem + TILE_B + off)       = ul;
            *(uint2*)(smem + 2 * TILE_B + off)   = pbh[i];
            *(uint2*)(smem + 3 * TILE_B + off)   = pbl[i];
        }
        __syncthreads();

        // ---- prefetch chunk c+1 ----
        if (c < 3) {
            const int kb = (c + 1) * 64;
#pragma unroll
            for (int i = 0; i < 8; i++) {
                const int row = bm + r0 + i * 16;
                pa[i] = make_float4(0.f, 0.f, 0.f, 0.f);
                if (row < M)
                    pa[i] = *(const float4*)(A + (size_t)row * 256 + kb + g * 4);
                const size_t src = (size_t)(wtrow + bn + r0 + i * 16) * 256 + kb + g * 4;
                pbh[i] = *(const uint2*)(g_wt_hi + src);
                pbl[i] = *(const uint2*)(g_wt_lo + src);
            }
        }

        // ---- MMA over 4 k16 steps ----
#pragma unroll
        for (int ks = 0; ks < 4; ks++) {
            const uint32_t kadd = (uint32_t)(ks * 16 * 2);
            uint32_t ahf[2][4], alf[2][4], bhf[4][4], blf[4][4];
#pragma unroll
            for (int mi = 0; mi < 2; mi++) {
                const uint32_t ao = aoff + (uint32_t)(mi * 16 * RS * 2) + kadd;
                ldm_x4(ahf[mi], sAh + ao);
                ldm_x4(alf[mi], sAl + ao);
            }
#pragma unroll
            for (int jj = 0; jj < 4; jj++) {
                const uint32_t bo = boff + (uint32_t)(jj * 16 * RS * 2) + kadd;
                ldm_x4(bhf[jj], sBh + bo);
                ldm_x4(blf[jj], sBl + bo);
            }
#pragma unroll
            for (int mi = 0; mi < 2; mi++)
#pragma unroll
                for (int j = 0; j < 8; j++) {
                    const int jj = j >> 1, sel = j & 1;
                    const uint32_t b0h = bhf[jj][sel], b1h = bhf[jj][sel + 2];
                    const uint32_t b0l = blf[jj][sel], b1l = blf[jj][sel + 2];
                    mma16816(acc[mi][j], ahf[mi], b0h, b1h);  // Ah*Bh
                    mma16816(acc[mi][j], ahf[mi], b0l, b1l);  // Ah*Bl
                    mma16816(acc[mi][j], alf[mi], b0h, b1h);  // Al*Bh
                }
        }
        __syncthreads();
    }

    // ---- epilogue: reg -> gmem with bias ----
    const int gcol0 = bn + wn * 64;
    const float* bp = bias1;
    int cb = 0;
    if (gcol0 >= nsplit) { bp = bias2; cb = nsplit; }

    const int rq = lane >> 2;        // 0..7
    const int cq = (lane & 3) * 2;   // 0,2,4,6
#pragma unroll
    for (int mi = 0; mi < 2; mi++) {
#pragma unroll
        for (int j = 0; j < 8; j++) {
            const int col = gcol0 + j * 8 + cq;
            const float2 bv = *(const float2*)(bp + (col - cb));
            const int row0 = bm + wm * 32 + mi * 16 + rq;
            if (row0 < M) {
                float2 v = make_float2(acc[mi][j][0] + bv.x, acc[mi][j][1] + bv.y);
                *(float2*)(C + (size_t)row0 * ldc + col) = v;
            }
            if (row0 + 8 < M) {
                float2 v = make_float2(acc[mi][j][2] + bv.x, acc[mi][j][3] + bv.y);
                *(float2*)(C + (size_t)(row0 + 8) * ldc + col) = v;
            }
        }
    }
}

// ---- sampler v2: 4 heads/warp, float4 lanes, owner/consumer split ----------
__global__ __launch_bounds__(256) void msda_sample_v2(
    const float* __restrict__ rp, const int* __restrict__ shapes, int M)
{
    __shared__ int s_w[4], s_h[4], s_start[4];
    __shared__ float s_fw[4], s_fh[4];
    __shared__ int s_L;
    if (threadIdx.x == 0) {
        int st = 0;
        for (int l = 0; l < 4; l++) {
            int hh = shapes[2 * l], ww = shapes[2 * l + 1];
            s_h[l] = hh; s_w[l] = ww; s_start[l] = st;
            s_fh[l] = (float)hh; s_fw[l] = (float)ww;
            st += hh * ww;
        }
        s_L = st;
    }
    __syncthreads();
    const int Ltot = s_L;

    const unsigned FULL = 0xffffffffu;
    const int lane = threadIdx.x & 31;
    const int warp = threadIdx.x >> 5;
    const int t = blockIdx.x * 4 + (warp >> 1);
    if (t >= M) return;
    const int h   = (warp & 1) * 4 + (lane >> 3);
    const int sub = lane & 7;
    const int b   = t / Ltot;

    float logit0, logit1;
    int   pi[2], pst[2];
    float pc00[2], pc10[2], pc01[2], pc11[2];
    {
        const float* ab = g_offattn + (size_t)t * 384 + 256 + h * 16;
        logit0 = ab[sub * 2];
        logit1 = ab[sub * 2 + 1];
    }
    float mx = fmaxf(logit0, logit1);
#pragma unroll
    for (int s = 4; s; s >>= 1) mx = fmaxf(mx, __shfl_xor_sync(FULL, mx, s));
    float e0 = expf(logit0 - mx), e1 = expf(logit1 - mx);
    float sm = e0 + e1;
#pragma unroll
    for (int s = 4; s; s >>= 1) sm += __shfl_xor_sync(FULL, sm, s);
    const float inv = 1.f / sm;

#pragma unroll
    for (int s = 0; s < 2; s++) {
        const int pt = sub * 2 + s;
        const int l  = pt >> 2;
        const float aw = (s ? e1 : e0) * inv;
        float2 off = *(const float2*)(g_offattn + (size_t)t * 384 + h * 32 + pt * 2);
        float2 ref = *(const float2*)(rp + (size_t)t * 8 + l * 2);
        const int w_ = s_w[l], h_ = s_h[l];
        const float x = (ref.x + off.x) * s_fw[l] - 0.5f;
        const float y = (ref.y + off.y) * s_fh[l] - 0.5f;
        const float x0f = floorf(x), y0f = floorf(y);
        const float fx = x - x0f, fy = y - y0f;
        const int x0 = (int)x0f, y0 = (int)y0f;
        const float m00 = ((x0 >= 0)     & (x0 < w_)     & (y0 >= 0)     & (y0 < h_))     ? 1.f : 0.f;
        const float m10 = ((x0 + 1 >= 0) & (x0 + 1 < w_) & (y0 >= 0)     & (y0 < h_))     ? 1.f : 0.f;
        const float m01 = ((x0 >= 0)     & (x0 < w_)     & (y0 + 1 >= 0) & (y0 + 1 < h_)) ? 1.f : 0.f;
        const float m11 = ((x0 + 1 >= 0) & (x0 + 1 < w_) & (y0 + 1 >= 0) & (y0 + 1 < h_)) ? 1.f : 0.f;
        const int xc0 = min(max(x0, 0), w_ - 1);
        const int xc1 = min(max(x0 + 1, 0), w_ - 1);
        const int yc0 = min(max(y0, 0), h_ - 1);
        const int yc1 = min(max(y0 + 1, 0), h_ - 1);
        pi[s]  = s_start[l] + yc0 * w_ + xc0;
        pst[s] = (xc1 - xc0) | ((yc1 - yc0) * w_ << 16);
        const float gx1 = fx, gx0 = 1.f - fx;
        const float gy1 = fy, gy0 = 1.f - fy;
        pc00[s] = gx0 * gy0 * m00 * aw;
        pc10[s] = gx1 * gy0 * m10 * aw;
        pc01[s] = gx0 * gy1 * m01 * aw;
        pc11[s] = gx1 * gy1 * m11 * aw;
    }

    const float4* vp = (const float4*)g_value + (size_t)b * Ltot * 64 + h * 8 + sub;
    float4 acc = make_float4(0.f, 0.f, 0.f, 0.f);
#pragma unroll
    for (int pt = 0; pt < 16; pt++) {
        const int src  = pt >> 1;
        const int slot = pt & 1;
        const int   i00 = slot ? __shfl_sync(FULL, pi[1],   src, 8) : __shfl_sync(FULL, pi[0],   src, 8);
        const int   st  = slot ? __shfl_sync(FULL, pst[1],  src, 8) : __shfl_sync(FULL, pst[0],  src, 8);
        const float c00 = slot ? __shfl_sync(FULL, pc00[1], src, 8) : __shfl_sync(FULL, pc00[0], src, 8);
        const float c10 = slot ? __shfl_sync(FULL, pc10[1], src, 8) : __shfl_sync(FULL, pc10[0], src, 8);
        const float c01 = slot ? __shfl_sync(FULL, pc01[1], src, 8) : __shfl_sync(FULL, pc01[0], src, 8);
        const float c11 = slot ? __shfl_sync(FULL, pc11[1], src, 8) : __shfl_sync(FULL, pc11[0], src, 8);
        const int cs = st & 0xffff;
        const int rs = st >> 16;
        const float4* q = vp + (size_t)i00 * 64;
        const float4 v00 = q[0];
        const float4 v10 = q[cs * 64];
        const float4 v01 = q[rs * 64];
        const float4 v11 = q[(cs + rs) * 64];
        acc.x = fmaf(c00, v00.x, fmaf(c10, v10.x, fmaf(c01, v01.x, fmaf(c11, v11.x, acc.x))));
        acc.y = fmaf(c00, v00.y, fmaf(c10, v10.y, fmaf(c01, v01.y, fmaf(c11, v11.y, acc.y))));
        acc.z = fmaf(c00, v00.z, fmaf(c10, v10.z, fmaf(c01, v01.z, fmaf(c11, v11.z, acc.z))));
        acc.w = fmaf(c00, v00.w, fmaf(c10, v10.w, fmaf(c01, v01.w, fmaf(c11, v11.w, acc.w))));
    }
    *(float4*)(g_msda + (size_t)t * 256 + h * 32 + sub * 4) = acc;
}

// ---------------------------------------------------------------------------
extern "C" void kernel_launch(void* const* d_in, const int* in_sizes, int n_in,
                              void* d_out, int out_size)
{
    const float* query   = (const float*)d_in[0];
    const float* rp      = (const float*)d_in[1];
    const float* flat    = (const float*)d_in[2];
    const int*   shapes  = (const int*)  d_in[3];
    const float* W_off   = (const float*)d_in[4];
    const float* b_off   = (const float*)d_in[5];
    const float* W_attn  = (const float*)d_in[6];
    const float* b_attn  = (const float*)d_in[7];
    const float* W_val   = (const float*)d_in[8];
    const float* b_val   = (const float*)d_in[9];
    const float* W_out   = (const float*)d_in[10];
    const float* b_out   = (const float*)d_in[11];
    float* out = (float*)d_out;

    const int M = in_sizes[0] / 256;

    float *pv, *poa, *pm;
    cudaGetSymbolAddress((void**)&pv,  g_value);
    cudaGetSymbolAddress((void**)&poa, g_offattn);
    cudaGetSymbolAddress((void**)&pm,  g_msda);

    cudaFuncSetAttribute(gemm_mma, cudaFuncAttributeMaxDynamicSharedMemorySize,
                         SM_GEMM);

    const int mtiles = (M + 127) / 128;

    wt_convert<<<896, 256>>>(W_val, W_off, W_attn, W_out);
    // value projection: N=256
    gemm_mma<<<dim3(2, mtiles), 256, SM_GEMM>>>(flat, 0, b_val, b_val, 256,
                                                pv, 256, M, 256);
    // fused offsets+attn: N=384, split at 256
    gemm_mma<<<dim3(3, mtiles), 256, SM_GEMM>>>(query, 256, b_off, b_attn, 256,
                                                poa, 384, M, 384);
    msda_sample_v2<<<dim3((M + 3) / 4), 256>>>(rp, shapes, M);
    // output projection: N=256
    gemm_mma<<<dim3(2, mtiles), 256, SM_GEMM>>>(pm, 640, b_out, b_out, 256,
                                                out, 256, M, 256);
}